// round 6
// baseline (speedup 1.0000x reference)
#include <cuda_runtime.h>
#include <cuda_bf16.h>
#include <cstdint>

// ============================================================================
// InteractionPruning: out[b,i,j] = f_i^T Z_ij f_j,  Z = clip(sig(M)*1.2-0.1,0,1)
// Split: Z = 0.5 + R,  R = clip(0.6*tanh(M/2), -0.5, 0.5)
//   out = 0.5*S_i*S_j (fp32 exact)  +  f_i^T R f_j (bf16 mma.sync HMMA)
// v5: CTA = (pair, 4-bt group) -> R frags loaded once per 4 bt (L2 traffic
//     381->285MB), double-buffered A via cp.async ping-pong; preps merged into
//     one 1504-block kernel with coalesced loads + conflict-free frag gathers.
// ============================================================================

#define B_SZ   1024
#define F_SZ   32
#define D_SZ   128
#define NPAIR  496
#define NBT    8

// g_FA: A-frag images of feature:  [bt][f] x (mt8 x ks8 x lane32) uint4 = 32KB/tile
// g_RB: B-frag images of R:        [p]    x (nt16 x ks8 x lane32) uint2 = 32KB/pair
__device__ uint4 g_FA[NBT * F_SZ * 2048];   // 8 MB
__device__ uint4 g_RB[NPAIR * 2048];        // 15.9 MB
__device__ float g_S[B_SZ * F_SZ];          // row sums of feature

// ---------------------------------------------------------------------------
__device__ __forceinline__ void decode_pair(int p, int& i, int& j) {
    int jj = (int)((1.0f + sqrtf(1.0f + 8.0f * (float)p)) * 0.5f);
    while (jj * (jj - 1) / 2 > p) --jj;
    while ((jj + 1) * jj / 2 <= p) ++jj;
    j = jj;
    i = p - jj * (jj - 1) / 2;
}

__device__ __forceinline__ float gate_r(float m) {
    float x = 0.5f * m;
    if (fabsf(m) < 0.04f) {
        return 0.6f * (x - 0.33333334f * x * x * x);   // rel err < 1e-7
    }
    float s = 1.0f / (1.0f + __expf(-m));
    return fminf(fmaxf(1.2f * s - 0.6f, -0.5f), 0.5f);
}

__device__ __forceinline__ uint32_t pack_bf16x2(float a, float b) {
    return (uint32_t)__bfloat16_as_ushort(__float2bfloat16(a)) |
           ((uint32_t)__bfloat16_as_ushort(__float2bfloat16(b)) << 16);
}

__device__ __forceinline__ float2 bf2_to_f2(uint32_t u) {
    __nv_bfloat162 h = *reinterpret_cast<__nv_bfloat162*>(&u);
    return __bfloat1622float2(h);
}

__device__ __forceinline__ void mma16816(float* c, const uint32_t* a, const uint32_t* b) {
    asm volatile(
        "mma.sync.aligned.m16n8k16.row.col.f32.bf16.bf16.f32 "
        "{%0,%1,%2,%3}, {%4,%5,%6,%7}, {%8,%9}, {%0,%1,%2,%3};"
        : "+f"(c[0]), "+f"(c[1]), "+f"(c[2]), "+f"(c[3])
        : "r"(a[0]), "r"(a[1]), "r"(a[2]), "r"(a[3]), "r"(b[0]), "r"(b[1]));
}

#define CP_ASYNC16(dst_u32, src_ptr) \
    asm volatile("cp.async.cg.shared.global [%0], [%1], 16;" \
                 :: "r"(dst_u32), "l"(src_ptr) : "memory")
#define CP_COMMIT() asm volatile("cp.async.commit_group;" ::: "memory")
#define CP_WAIT_ALL() asm volatile("cp.async.wait_group 0;" ::: "memory")

// ---------------------------------------------------------------------------
// prep_all: 1504 blocks x 256 threads.
//   blocks [0,512):    feature half-tiles -> A-frags + row sums S + zero out
//   blocks [512,1504): R half-tiles -> B-frags (gate + pack)
// Both use: coalesced float4 row loads -> bf16x2 smem stage (stride 68 dwords,
// conflict-free gathers) -> coalesced fragment writes.
// ---------------------------------------------------------------------------
__global__ void __launch_bounds__(256) prep_all(const float* __restrict__ feature,
                                                const float* __restrict__ matrix,
                                                float4* __restrict__ out4) {
    __shared__ uint32_t stage[64 * 68];
    __shared__ float ssum[64];

    int tid = threadIdx.x, bid = blockIdx.x;
    int lane = tid & 31, w = tid >> 5;

    if (bid < 512) {
        // ---------------- feature half-tile ----------------
        int h = bid & 1, f = (bid >> 1) & 31, bt = bid >> 6;
        const float4* src = reinterpret_cast<const float4*>(
            feature + ((size_t)(bt * 128 + h * 64) * F_SZ + f) * D_SZ);
#pragma unroll
        for (int it = 0; it < 8; it++) {
            int rl = it * 8 + w;                      // local row 0..63
            float4 v = src[(size_t)rl * 1024 + lane]; // row stride F*D/4=1024
            stage[rl * 68 + lane * 2]     = pack_bf16x2(v.x, v.y);
            stage[rl * 68 + lane * 2 + 1] = pack_bf16x2(v.z, v.w);
            float s = v.x + v.y + v.z + v.w;
#pragma unroll
            for (int o = 16; o; o >>= 1) s += __shfl_xor_sync(0xffffffffu, s, o);
            if (lane == 0) ssum[rl] = s;
        }
        __syncthreads();

        if (tid < 64) g_S[(bt * 128 + h * 64 + tid) * F_SZ + f] = ssum[tid];

        // zero out buffer: 262144 float4 / 512 blocks = 512 / block
#pragma unroll
        for (int z = 0; z < 2; z++)
            out4[(size_t)bid * 512 + z * 256 + tid] = make_float4(0.f, 0.f, 0.f, 0.f);

        // A-fragment gathers (conflict-free) + coalesced uint4 writes
        uint4* dst = g_FA + (size_t)(bt * F_SZ + f) * 2048;
#pragma unroll
        for (int mtl = 0; mtl < 4; mtl++) {
            int mt = h * 4 + mtl;
            int b0 = mtl * 16 + (lane >> 2), b1 = b0 + 8;
            int c = w * 8 + (lane & 3);
            uint4 o;
            o.x = stage[b0 * 68 + c];
            o.y = stage[b1 * 68 + c];
            o.z = stage[b0 * 68 + c + 4];
            o.w = stage[b1 * 68 + c + 4];
            dst[(mt * 8 + w) * 32 + lane] = o;
        }
    } else {
        // ---------------- R half-tile ----------------
        int idx = bid - 512;
        int h = idx & 1, p = idx >> 1;
        int i, j; decode_pair(p, i, j);
        const float4* src = reinterpret_cast<const float4*>(
            matrix + (((size_t)(i * F_SZ + j) * D_SZ) + h * 64) * D_SZ);
#pragma unroll
        for (int it = 0; it < 8; it++) {
            int rl = it * 8 + w;                      // local d row 0..63
            float4 v = src[(size_t)rl * 32 + lane];   // row stride D/4=32
            stage[rl * 68 + lane * 2]     = pack_bf16x2(gate_r(v.x), gate_r(v.y));
            stage[rl * 68 + lane * 2 + 1] = pack_bf16x2(gate_r(v.z), gate_r(v.w));
        }
        __syncthreads();

        // B-frag: b0 = {R[d][k0],R[d][k0+1]} = stage dword (ks*8+(lane&3)),
        //         b1 = same +8 cols -> +4 dwords
        uint2* dst = reinterpret_cast<uint2*>(g_RB) + (size_t)p * 4096;
#pragma unroll
        for (int ntl = 0; ntl < 8; ntl++) {
            int nt = h * 8 + ntl;
            int dl = ntl * 8 + (lane >> 2);
            int c = w * 8 + (lane & 3);
            uint2 o;
            o.x = stage[dl * 68 + c];
            o.y = stage[dl * 68 + c + 4];
            dst[(nt * 8 + w) * 32 + lane] = o;
        }
    }
}

// ---------------------------------------------------------------------------
// Main kernel: CTA = (pair p, 4-bt group). 4 warps, 32 batch rows each.
// SMEM: sB (R frags 32KB) | sA0 | sA1 (double-buffered Fj frags) = 96KB.
// R loaded once per CTA; A tiles ping-pong under compute; Fi via prefetch LDG.
// ---------------------------------------------------------------------------
__global__ void __launch_bounds__(128, 2) main_mma(float* __restrict__ out) {
    extern __shared__ char sm[];
    int tid = threadIdx.x, w = tid >> 5, lane = tid & 31;
    int p = blockIdx.x >> 1, btg = blockIdx.x & 1;
    int i, j; decode_pair(p, i, j);

    uint32_t sb = 0;
    asm("{ .reg .u64 t; cvta.to.shared.u64 t, %1; cvt.u32.u64 %0, t; }"
        : "=r"(sb) : "l"(sm));

    const uint4* gB = g_RB + (size_t)p * 2048;

    // group 0: B frags + A(bt0)
#pragma unroll
    for (int k = 0; k < 16; k++)
        CP_ASYNC16(sb + (uint32_t)(tid + 128 * k) * 16, (const void*)(gB + tid + 128 * k));
    {
        const uint4* gA = g_FA + (size_t)((btg * 4 + 0) * F_SZ + j) * 2048;
#pragma unroll
        for (int k = 0; k < 16; k++)
            CP_ASYNC16(sb + 32768u + (uint32_t)(tid + 128 * k) * 16,
                       (const void*)(gA + tid + 128 * k));
    }
    CP_COMMIT();

    const uint2* sB = reinterpret_cast<const uint2*>(sm);   // [nt16][ks8][lane32]

#pragma unroll
    for (int t = 0; t < 4; t++) {
        int bt = btg * 4 + t;
        uint32_t bufo = 32768u + (uint32_t)(t & 1) * 32768u;
        const uint4* sA = reinterpret_cast<const uint4*>(sm + bufo);

        CP_WAIT_ALL();
        __syncthreads();

        // load A fragments for this warp's 32 rows (mtiles 2w, 2w+1)
        uint32_t Afr[2][8][4];
#pragma unroll
        for (int mt = 0; mt < 2; mt++) {
#pragma unroll
            for (int ks = 0; ks < 8; ks++) {
                uint4 v = sA[((2 * w + mt) * 8 + ks) * 32 + lane];
                Afr[mt][ks][0] = v.x; Afr[mt][ks][1] = v.y;
                Afr[mt][ks][2] = v.z; Afr[mt][ks][3] = v.w;
            }
        }
        __syncthreads();

        // prefetch next A tile into the other buffer (overlaps with MMA below)
        if (t < 3) {
            const uint4* gA = g_FA + (size_t)((bt + 1) * F_SZ + j) * 2048;
            uint32_t nbuf = 32768u + (uint32_t)((t + 1) & 1) * 32768u;
#pragma unroll
            for (int k = 0; k < 16; k++)
                CP_ASYNC16(sb + nbuf + (uint32_t)(tid + 128 * k) * 16,
                           (const void*)(gA + tid + 128 * k));
            CP_COMMIT();
        }

        const uint4* gC = g_FA + (size_t)(bt * F_SZ + i) * 2048;
        float pacc[2][2] = {{0.f, 0.f}, {0.f, 0.f}};

#pragma unroll
        for (int g4 = 0; g4 < 4; g4++) {            // n (=d) in 4 groups of 32
            // prefetch Fi epilogue frags (coalesced LDG.128, L2-hit)
            uint4 cf[2][2];
#pragma unroll
            for (int mt = 0; mt < 2; mt++)
#pragma unroll
                for (int s2 = 0; s2 < 2; s2++)
                    cf[mt][s2] = gC[((2 * w + mt) * 8 + (g4 * 2 + s2)) * 32 + lane];

            float acc[2][4][4];
#pragma unroll
            for (int mt = 0; mt < 2; mt++)
#pragma unroll
                for (int nt = 0; nt < 4; nt++)
#pragma unroll
                    for (int q = 0; q < 4; q++) acc[mt][nt][q] = 0.f;

#pragma unroll
            for (int ks = 0; ks < 8; ks++) {
                uint32_t Bfr[4][2];
#pragma unroll
                for (int nt = 0; nt < 4; nt++) {
                    uint2 v = sB[((g4 * 4 + nt) * 8 + ks) * 32 + lane];
                    Bfr[nt][0] = v.x; Bfr[nt][1] = v.y;
                }
#pragma unroll
                for (int mt = 0; mt < 2; mt++)
#pragma unroll
                    for (int nt = 0; nt < 4; nt++)
                        mma16816(acc[mt][nt], Afr[mt][ks], Bfr[nt]);
            }

            // group epilogue: dot with Fi frags
#pragma unroll
            for (int mt = 0; mt < 2; mt++) {
#pragma unroll
                for (int s2 = 0; s2 < 2; s2++) {
                    uint4 v = cf[mt][s2];
                    float2 lo0 = bf2_to_f2(v.x), hi0 = bf2_to_f2(v.y);
                    pacc[mt][0] += acc[mt][2 * s2][0] * lo0.x + acc[mt][2 * s2][1] * lo0.y;
                    pacc[mt][1] += acc[mt][2 * s2][2] * hi0.x + acc[mt][2 * s2][3] * hi0.y;
                    float2 lo1 = bf2_to_f2(v.z), hi1 = bf2_to_f2(v.w);
                    pacc[mt][0] += acc[mt][2 * s2 + 1][0] * lo1.x + acc[mt][2 * s2 + 1][1] * lo1.y;
                    pacc[mt][1] += acc[mt][2 * s2 + 1][2] * hi1.x + acc[mt][2 * s2 + 1][3] * hi1.y;
                }
            }
        }

        // quad reduce + write
#pragma unroll
        for (int mt = 0; mt < 2; mt++)
#pragma unroll
            for (int hh = 0; hh < 2; hh++) {
                pacc[mt][hh] += __shfl_xor_sync(0xffffffffu, pacc[mt][hh], 1);
                pacc[mt][hh] += __shfl_xor_sync(0xffffffffu, pacc[mt][hh], 2);
            }

        if ((lane & 3) == 0) {
#pragma unroll
            for (int mt = 0; mt < 2; mt++) {
#pragma unroll
                for (int hh = 0; hh < 2; hh++) {
                    int row = (2 * w + mt) * 16 + (lane >> 2) + hh * 8;
                    int bg = bt * 128 + row;
                    float res = 0.5f * g_S[bg * F_SZ + i] * g_S[bg * F_SZ + j] + pacc[mt][hh];
                    out[(size_t)bg * (F_SZ * F_SZ) + i * F_SZ + j] = res;
                }
            }
        }
    }
}

// ---------------------------------------------------------------------------
extern "C" void kernel_launch(void* const* d_in, const int* in_sizes, int n_in,
                              void* d_out, int out_size) {
    const float* feature = (const float*)d_in[0];   // [1024, 32, 128] f32
    const float* matrix  = (const float*)d_in[1];   // [32, 32, 128, 128] f32
    float* out = (float*)d_out;                     // [1024, 32, 32] f32

    cudaFuncSetAttribute(main_mma, cudaFuncAttributeMaxDynamicSharedMemorySize, 98304);

    prep_all<<<512 + 2 * NPAIR, 256>>>(feature, matrix, (float4*)out);  // 1504 blocks
    main_mma<<<NPAIR * 2, 128, 98304>>>(out);                           // 992 blocks
}

// round 8
// speedup vs baseline: 1.2813x; 1.2813x over previous
#include <cuda_runtime.h>
#include <cuda_bf16.h>
#include <cuda_fp16.h>
#include <cstdint>

// ============================================================================
// InteractionPruning: out[b,i,j] = f_i^T Z_ij f_j,  Z = clip(sig(M)*1.2-0.1,0,1)
// Split: Z = 0.5 + R,  R = clip(0.6*tanh(M/2), -0.5, 0.5)
//   out = 0.5*S_i*S_j (fp32 exact)  +  f_i^T R f_j  (e4m3 mma.sync m16n8k32)
// v7: fp8 path. R scaled by 2^17 into e4m3. Per-unit L2 traffic 96->48KB
//     (A16 + B16 + C16, C extracted from the fp8 A-image of tile i).
//     Grid back to 3968 (p,bt), 32KB smem, light registers.
// ============================================================================

#define B_SZ   1024
#define F_SZ   32
#define D_SZ   128
#define NPAIR  496
#define NBT    8

#define R_SCALE     131072.0f      // 2^17
#define R_INVSCALE  (1.0f/131072.0f)

// g_FA8: fp8 A-frag images of feature: [bt][f] x (mt8 x ksg4 x lane32) uint4 = 16KB/tile
// g_RB8: fp8 B-frag images of R:       [p]    x (nt16 x ksg4 x lane32) uint2 = 16KB/pair
__device__ uint4 g_FA8[NBT * F_SZ * 1024];   // 4 MB
__device__ uint2 g_RB8[NPAIR * 2048];        // 7.9 MB
__device__ float g_S[B_SZ * F_SZ];           // row sums of feature

// ---------------------------------------------------------------------------
__device__ __forceinline__ void decode_pair(int p, int& i, int& j) {
    int jj = (int)((1.0f + sqrtf(1.0f + 8.0f * (float)p)) * 0.5f);
    while (jj * (jj - 1) / 2 > p) --jj;
    while ((jj + 1) * jj / 2 <= p) ++jj;
    j = jj;
    i = p - jj * (jj - 1) / 2;
}

__device__ __forceinline__ float gate_r(float m) {
    float x = 0.5f * m;
    if (fabsf(m) < 0.04f) {
        return 0.6f * (x - 0.33333334f * x * x * x);   // rel err < 1e-7
    }
    float s = 1.0f / (1.0f + __expf(-m));
    return fminf(fmaxf(1.2f * s - 0.6f, -0.5f), 0.5f);
}

// pack 4 floats -> 4 e4m3 bytes (f0 lowest byte)
__device__ __forceinline__ uint32_t pack_e4m3x4(float f0, float f1, float f2, float f3) {
    unsigned short lo, hi;
    asm("cvt.rn.satfinite.e4m3x2.f32 %0, %1, %2;" : "=h"(lo) : "f"(f1), "f"(f0));
    asm("cvt.rn.satfinite.e4m3x2.f32 %0, %1, %2;" : "=h"(hi) : "f"(f3), "f"(f2));
    return (uint32_t)lo | ((uint32_t)hi << 16);
}

// select fp8 pair (sel=0: bytes 0-1, sel=1: bytes 2-3) -> float2
__device__ __forceinline__ float2 fp8pair_to_f2(uint32_t dw, int sel) {
    unsigned short h = (unsigned short)(sel ? (dw >> 16) : dw);
    uint32_t h2;
    asm("cvt.rn.f16x2.e4m3x2 %0, %1;" : "=r"(h2) : "h"(h));
    __half2 hh = *reinterpret_cast<__half2*>(&h2);
    return __half22float2(hh);
}

// mma.sync m16n8k32 row.col f32 += e4m3*e4m3
__device__ __forceinline__ void mma16832(float* c, const uint32_t* a, const uint32_t* b) {
    asm volatile(
        "mma.sync.aligned.m16n8k32.row.col.f32.e4m3.e4m3.f32 "
        "{%0,%1,%2,%3}, {%4,%5,%6,%7}, {%8,%9}, {%0,%1,%2,%3};"
        : "+f"(c[0]), "+f"(c[1]), "+f"(c[2]), "+f"(c[3])
        : "r"(a[0]), "r"(a[1]), "r"(a[2]), "r"(a[3]), "r"(b[0]), "r"(b[1]));
}

#define CP_ASYNC16(dst_u32, src_ptr) \
    asm volatile("cp.async.cg.shared.global [%0], [%1], 16;" \
                 :: "r"(dst_u32), "l"(src_ptr) : "memory")
#define CP_COMMIT() asm volatile("cp.async.commit_group;" ::: "memory")
#define CP_WAIT_GROUP(n) asm volatile("cp.async.wait_group %0;" :: "n"(n) : "memory")

// ---------------------------------------------------------------------------
// prep_all: 1504 blocks x 256 threads.
//   blocks [0,512):    feature half-tiles -> fp8 A-frags + row sums S + zero out
//   blocks [512,1504): R half-tiles -> fp8 B-frags (gate + scale + pack)
// Stage: 64 rows x 32 fp8x4-dwords, stride 36 -> conflict-free frag gathers.
// ---------------------------------------------------------------------------
__global__ void __launch_bounds__(256) prep_all(const float* __restrict__ feature,
                                                const float* __restrict__ matrix,
                                                float4* __restrict__ out4) {
    __shared__ uint32_t stage[64 * 36];
    __shared__ float ssum[64];

    int tid = threadIdx.x, bid = blockIdx.x;
    int lane = tid & 31, w = tid >> 5;

    if (bid < 512) {
        // ---------------- feature half-tile ----------------
        int h = bid & 1, f = (bid >> 1) & 31, bt = bid >> 6;
        const float4* src = reinterpret_cast<const float4*>(
            feature + ((size_t)(bt * 128 + h * 64) * F_SZ + f) * D_SZ);
#pragma unroll
        for (int it = 0; it < 8; it++) {
            int rl = it * 8 + w;                      // local row 0..63
            float4 v = src[(size_t)rl * 1024 + lane]; // row stride F*D/4=1024
            stage[rl * 36 + lane] = pack_e4m3x4(v.x, v.y, v.z, v.w);
            float s = v.x + v.y + v.z + v.w;
#pragma unroll
            for (int o = 16; o; o >>= 1) s += __shfl_xor_sync(0xffffffffu, s, o);
            if (lane == 0) ssum[rl] = s;
        }
        __syncthreads();

        if (tid < 64) g_S[(bt * 128 + h * 64 + tid) * F_SZ + f] = ssum[tid];

        // zero out buffer: 262144 float4 / 512 blocks = 512 per block
#pragma unroll
        for (int z = 0; z < 2; z++)
            out4[(size_t)bid * 512 + z * 256 + tid] = make_float4(0.f, 0.f, 0.f, 0.f);

        // A-frag gathers: 16 warp-tasks (mtl4 x ksg4), each warp does 2
        uint4* dst = g_FA8 + (size_t)(bt * F_SZ + f) * 1024;
#pragma unroll
        for (int t = 0; t < 2; t++) {
            int task = w + t * 8;
            int mtl = task >> 2, ksg = task & 3;
            int b0 = mtl * 16 + (lane >> 2), b1 = b0 + 8;
            int c = ksg * 8 + (lane & 3);
            uint4 o;
            o.x = stage[b0 * 36 + c];
            o.y = stage[b1 * 36 + c];
            o.z = stage[b0 * 36 + c + 4];
            o.w = stage[b1 * 36 + c + 4];
            int mt = h * 4 + mtl;
            dst[(mt * 4 + ksg) * 32 + lane] = o;
        }
    } else {
        // ---------------- R half-tile ----------------
        int idx = bid - 512;
        int h = idx & 1, p = idx >> 1;
        int i, j; decode_pair(p, i, j);
        const float4* src = reinterpret_cast<const float4*>(
            matrix + (((size_t)(i * F_SZ + j) * D_SZ) + h * 64) * D_SZ);
#pragma unroll
        for (int it = 0; it < 8; it++) {
            int rl = it * 8 + w;                      // local d row 0..63
            float4 v = src[(size_t)rl * 32 + lane];   // row stride D/4=32
            stage[rl * 36 + lane] = pack_e4m3x4(gate_r(v.x) * R_SCALE,
                                                gate_r(v.y) * R_SCALE,
                                                gate_r(v.z) * R_SCALE,
                                                gate_r(v.w) * R_SCALE);
        }
        __syncthreads();

        // B-frag gathers: 32 warp-tasks (ntl8 x ksg4), each warp does 4
        uint2* dst = g_RB8 + (size_t)p * 2048;
#pragma unroll
        for (int t = 0; t < 4; t++) {
            int task = w * 4 + t;
            int ntl = task >> 2, ksg = task & 3;
            int dl = ntl * 8 + (lane >> 2);
            int c = ksg * 8 + (lane & 3);
            uint2 o;
            o.x = stage[dl * 36 + c];
            o.y = stage[dl * 36 + c + 4];
            int nt = h * 8 + ntl;
            dst[(nt * 4 + ksg) * 32 + lane] = o;
        }
    }
}

// ---------------------------------------------------------------------------
// Main kernel: CTA = (pair p, batch tile bt). 4 warps, 32 batch rows each.
// SMEM: sA (Fj fp8 A-frags 16KB) | sB (R fp8 B-frags 16KB) = 32KB.
// Fi epilogue pairs extracted from the fp8 A-image of tile i via LDG + cvt.
// ---------------------------------------------------------------------------
__global__ void __launch_bounds__(128, 3) main_mma(float* __restrict__ out) {
    extern __shared__ char sm[];
    int tid = threadIdx.x, w = tid >> 5, lane = tid & 31;
    int p = blockIdx.x >> 3, bt = blockIdx.x & 7;
    int i, j; decode_pair(p, i, j);

    uint32_t sb = 0;
    asm("{ .reg .u64 t; cvta.to.shared.u64 t, %1; cvt.u32.u64 %0, t; }"
        : "=r"(sb) : "l"(sm));

    const uint4* gA = g_FA8 + (size_t)(bt * F_SZ + j) * 1024;
    const uint4* gB = reinterpret_cast<const uint4*>(g_RB8) + (size_t)p * 1024;
    const uint4* gC = g_FA8 + (size_t)(bt * F_SZ + i) * 1024;

#pragma unroll
    for (int k = 0; k < 8; k++)
        CP_ASYNC16(sb + (uint32_t)(tid + 128 * k) * 16, (const void*)(gA + tid + 128 * k));
    CP_COMMIT();
#pragma unroll
    for (int k = 0; k < 8; k++)
        CP_ASYNC16(sb + 16384u + (uint32_t)(tid + 128 * k) * 16, (const void*)(gB + tid + 128 * k));
    CP_COMMIT();

    const uint4* sA = reinterpret_cast<const uint4*>(sm);           // [mt8][ksg4][lane32]
    const uint2* sB = reinterpret_cast<const uint2*>(sm + 16384);   // [nt16][ksg4][lane32]

    CP_WAIT_GROUP(1);
    __syncthreads();

    // A fragments for this warp's 32 rows (mtiles 2w, 2w+1)
    uint32_t Afr[2][4][4];
#pragma unroll
    for (int mt = 0; mt < 2; mt++) {
#pragma unroll
        for (int ksg = 0; ksg < 4; ksg++) {
            uint4 v = sA[((2 * w + mt) * 4 + ksg) * 32 + lane];
            Afr[mt][ksg][0] = v.x; Afr[mt][ksg][1] = v.y;
            Afr[mt][ksg][2] = v.z; Afr[mt][ksg][3] = v.w;
        }
    }

    CP_WAIT_GROUP(0);
    __syncthreads();

    int sel = lane & 1;                // fp8 pair within dword = (lane&3)&1
    int lq  = ((lane & 3) >> 1);       // dword sub-select
    float pacc[2][2] = {{0.f, 0.f}, {0.f, 0.f}};

#pragma unroll
    for (int g4 = 0; g4 < 4; g4++) {                // n (=d) in 4 groups of 32
        // epilogue Fi dwords: frag image (mt''=2w+mt, ksg'=g4), remapped lane
        uint4 ep[2][2];
#pragma unroll
        for (int mt = 0; mt < 2; mt++) {
#pragma unroll
            for (int s = 0; s < 2; s++) {
                int lp = (lane >> 2) * 4 + s * 2 + lq;
                ep[mt][s] = gC[((2 * w + mt) * 4 + g4) * 32 + lp];
            }
        }

        float acc[2][4][4];
#pragma unroll
        for (int mt = 0; mt < 2; mt++)
#pragma unroll
            for (int nt = 0; nt < 4; nt++)
#pragma unroll
                for (int q = 0; q < 4; q++) acc[mt][nt][q] = 0.f;

#pragma unroll
        for (int ksg = 0; ksg < 4; ksg++) {
            uint32_t Bfr[4][2];
#pragma unroll
            for (int nt = 0; nt < 4; nt++) {
                uint2 v = sB[((g4 * 4 + nt) * 4 + ksg) * 32 + lane];
                Bfr[nt][0] = v.x; Bfr[nt][1] = v.y;
            }
#pragma unroll
            for (int mt = 0; mt < 2; mt++)
#pragma unroll
                for (int nt = 0; nt < 4; nt++)
                    mma16832(acc[mt][nt], Afr[mt][ksg], Bfr[nt]);
        }

        // epilogue: nt0 -> ep[mt][0].x/.y ; nt1 -> ep[mt][1].x/.y
        //           nt2 -> ep[mt][0].z/.w ; nt3 -> ep[mt][1].z/.w
#pragma unroll
        for (int mt = 0; mt < 2; mt++) {
#pragma unroll
            for (int nt = 0; nt < 4; nt++) {
                const uint4& e = ep[mt][nt & 1];
                uint32_t dw0 = (nt < 2) ? e.x : e.z;   // row0 dword
                uint32_t dw1 = (nt < 2) ? e.y : e.w;   // row1 dword
                float2 f0 = fp8pair_to_f2(dw0, sel);
                float2 f1 = fp8pair_to_f2(dw1, sel);
                pacc[mt][0] += acc[mt][nt][0] * f0.x + acc[mt][nt][1] * f0.y;
                pacc[mt][1] += acc[mt][nt][2] * f1.x + acc[mt][nt][3] * f1.y;
            }
        }
    }

    // quad reduce (cols live on lanes sharing lane>>2)
#pragma unroll
    for (int mt = 0; mt < 2; mt++)
#pragma unroll
        for (int hh = 0; hh < 2; hh++) {
            pacc[mt][hh] += __shfl_xor_sync(0xffffffffu, pacc[mt][hh], 1);
            pacc[mt][hh] += __shfl_xor_sync(0xffffffffu, pacc[mt][hh], 2);
        }

    if ((lane & 3) == 0) {
#pragma unroll
        for (int mt = 0; mt < 2; mt++) {
#pragma unroll
            for (int hh = 0; hh < 2; hh++) {
                int row = (2 * w + mt) * 16 + (lane >> 2) + hh * 8;
                int bg = bt * 128 + row;
                float res = 0.5f * g_S[bg * F_SZ + i] * g_S[bg * F_SZ + j]
                          + pacc[mt][hh] * R_INVSCALE;
                out[(size_t)bg * (F_SZ * F_SZ) + i * F_SZ + j] = res;
            }
        }
    }
}

// ---------------------------------------------------------------------------
extern "C" void kernel_launch(void* const* d_in, const int* in_sizes, int n_in,
                              void* d_out, int out_size) {
    const float* feature = (const float*)d_in[0];   // [1024, 32, 128] f32
    const float* matrix  = (const float*)d_in[1];   // [32, 32, 128, 128] f32
    float* out = (float*)d_out;                     // [1024, 32, 32] f32

    cudaFuncSetAttribute(main_mma, cudaFuncAttributeMaxDynamicSharedMemorySize, 32768);

    prep_all<<<512 + 2 * NPAIR, 256>>>(feature, matrix, (float4*)out);  // 1504 blocks
    main_mma<<<NPAIR * NBT, 128, 32768>>>(out);                         // 3968 blocks
}